// round 1
// baseline (speedup 1.0000x reference)
#include <cuda_runtime.h>
#include <math.h>

// ---------------------------------------------------------------------------
// MS-SSIM, 5 levels, inputs 16x3x512x512 fp32 (N*C = 48 planes, square, all
// level sizes even so avg_pool padding is always 0).
// Per level: fused tile kernel computes the 5 gaussian-blurred maps
// (mu1, mu2, E[XX], E[YY], E[XY]) via separable 11-tap blur in SMEM,
// epilogue -> per-plane sums of D=sqrt(2-S) and cs=S2 via block reduction +
// atomicAdd. Then a pool kernel halves X,Y for the next level.
// Final 1-block kernel does the weighted geometric combine.
// ---------------------------------------------------------------------------

#define TW 32
#define TH 32
#define EH 42          // TH + 10
#define EW 42          // TW + 10
#define EWP 43         // padded stride for input tiles (conflict-free)
#define HWP 33         // padded stride for horizontal-blur tiles

// scratch for pooled pyramids (levels 1..4), 48 planes each
// L1: 48*256*256 = 3145728   (offset 0)
// L2: 48*128*128 =  786432   (offset 3145728)
// L3: 48*64*64   =  196608   (offset 3932160)
// L4: 48*32*32   =   49152   (offset 4128768)   total 4177920
__device__ __align__(16) float d_Xp[4177920];
__device__ __align__(16) float d_Yp[4177920];
__device__ float d_sums[480];   // [level(5)][img(48)][2: d_sum, cs_sum]

__device__ __forceinline__ void gauss_init(float* g) {
    float s = 0.f;
#pragma unroll
    for (int k = 0; k < 11; k++) {
        float d = (float)(k - 5);
        g[k] = expf(-d * d * (1.0f / 4.5f));   // sigma = 1.5 -> 2*sigma^2 = 4.5
        s += g[k];
    }
    float inv = 1.0f / s;
#pragma unroll
    for (int k = 0; k < 11; k++) g[k] *= inv;
}

__global__ void zero_sums_kernel() {
    int i = threadIdx.x;
    if (i < 480) d_sums[i] = 0.f;
}

__global__ void __launch_bounds__(256) ssim_stats_kernel(
    const float* __restrict__ Xg, const float* __restrict__ Yg,
    int H, int W, int level)
{
    __shared__ float sX[EH][EWP];
    __shared__ float sY[EH][EWP];
    __shared__ float sH[5][EH][HWP];   // gx, gy, gxx, gyy, gxy (h-blurred)
    __shared__ float red[2][8];

    const int outH = H - 10, outW = W - 10;
    const int img = blockIdx.z;
    const int tx0 = blockIdx.x * TW;
    const int ty0 = blockIdx.y * TH;
    const float* Xi = Xg + (size_t)img * H * W;
    const float* Yi = Yg + (size_t)img * H * W;
    const int tid = threadIdx.x;

    float g[11];
    gauss_init(g);

    // ---- load extended tile (clamped; clamped values only feed masked px) --
    for (int i = tid; i < EH * EW; i += 256) {
        int r = i / EW, c = i - r * EW;
        int gr = ty0 + r; if (gr > H - 1) gr = H - 1;
        int gc = tx0 + c; if (gc > W - 1) gc = W - 1;
        size_t off = (size_t)gr * W + gc;
        sX[r][c] = Xi[off];
        sY[r][c] = Yi[off];
    }
    __syncthreads();

    // ---- horizontal blur: 42 rows x 32 cols, 4 consecutive cols per item ---
    for (int i = tid; i < EH * (TW / 4); i += 256) {
        int r = i >> 3, c4 = (i & 7) * 4;
        float bx[14], by[14];
#pragma unroll
        for (int j = 0; j < 14; j++) { bx[j] = sX[r][c4 + j]; by[j] = sY[r][c4 + j]; }
#pragma unroll
        for (int q = 0; q < 4; q++) {
            float gx = 0.f, gy = 0.f, gxx = 0.f, gyy = 0.f, gxy = 0.f;
#pragma unroll
            for (int k = 0; k < 11; k++) {
                float xv = bx[q + k], yv = by[q + k];
                float wx = g[k] * xv, wy = g[k] * yv;
                gx += wx; gy += wy;
                gxx = fmaf(wx, xv, gxx);
                gyy = fmaf(wy, yv, gyy);
                gxy = fmaf(wx, yv, gxy);
            }
            sH[0][r][c4 + q] = gx;
            sH[1][r][c4 + q] = gy;
            sH[2][r][c4 + q] = gxx;
            sH[3][r][c4 + q] = gyy;
            sH[4][r][c4 + q] = gxy;
        }
    }
    __syncthreads();

    // ---- vertical blur (4 consecutive rows per thread) + epilogue ----------
    const float C1 = 1e-4f, C2 = 9e-4f;
    float d_acc = 0.f, cs_acc = 0.f;
    const int ty = tid >> 5, tx = tid & 31;
    const int rbase = ty * 4;

    float m[5][4];
#pragma unroll
    for (int a = 0; a < 5; a++) {
        float buf[14];
#pragma unroll
        for (int j = 0; j < 14; j++) buf[j] = sH[a][rbase + j][tx];
#pragma unroll
        for (int q = 0; q < 4; q++) {
            float acc = 0.f;
#pragma unroll
            for (int k = 0; k < 11; k++) acc = fmaf(g[k], buf[q + k], acc);
            m[a][q] = acc;
        }
    }

    const int ocol = tx0 + tx;
#pragma unroll
    for (int q = 0; q < 4; q++) {
        int orow = ty0 + rbase + q;
        if (orow < outH && ocol < outW) {
            float mu1 = m[0][q], mu2 = m[1][q];
            float exx = m[2][q], eyy = m[3][q], exy = m[4][q];
            float mu1sq = mu1 * mu1, mu2sq = mu2 * mu2, mu12 = mu1 * mu2;
            float sig1 = exx - mu1sq, sig2 = eyy - mu2sq, sig12 = exy - mu12;
            float S1 = __fdividef(2.f * mu12 + C1, mu1sq + mu2sq + C1);
            float S2 = __fdividef(2.f * sig12 + C2, sig1 + sig2 + C2);
            float S = fminf(S1 + S2, 2.0f);
            d_acc += sqrtf(2.0f - S);
            cs_acc += S2;
        }
    }

    // ---- block reduce + atomic accumulate -----------------------------------
#pragma unroll
    for (int o = 16; o > 0; o >>= 1) {
        d_acc  += __shfl_down_sync(0xffffffffu, d_acc,  o);
        cs_acc += __shfl_down_sync(0xffffffffu, cs_acc, o);
    }
    if (tx == 0) { red[0][ty] = d_acc; red[1][ty] = cs_acc; }
    __syncthreads();
    if (tid == 0) {
        float ds = 0.f, cs = 0.f;
#pragma unroll
        for (int j = 0; j < 8; j++) { ds += red[0][j]; cs += red[1][j]; }
        atomicAdd(&d_sums[(level * 48 + img) * 2 + 0], ds);
        atomicAdd(&d_sums[(level * 48 + img) * 2 + 1], cs);
    }
}

// 2x2 average pool (all sizes even -> no padding), both tensors in one pass
__global__ void pool_kernel(const float* __restrict__ Xi, const float* __restrict__ Yi,
                            float* __restrict__ Xo, float* __restrict__ Yo,
                            int Ho, int Wi)
{
    const int Wo = Ho;
    const int total = 48 * Ho * Wo;
    int idx = blockIdx.x * blockDim.x + threadIdx.x;
    if (idx >= total) return;
    int w = idx % Wo;
    int t = idx / Wo;
    int h = t % Ho;
    int img = t / Ho;
    size_t base = (size_t)img * Wi * Wi + (size_t)(2 * h) * Wi + 2 * w;
    float2 a = *(const float2*)(Xi + base);
    float2 b = *(const float2*)(Xi + base + Wi);
    Xo[idx] = 0.25f * ((a.x + a.y) + (b.x + b.y));
    float2 c = *(const float2*)(Yi + base);
    float2 d = *(const float2*)(Yi + base + Wi);
    Yo[idx] = 0.25f * ((c.x + c.y) + (d.x + d.y));
}

// weighted geometric combine over levels, mean over (n,c)
__global__ void final_kernel(float* out, int out_size)
{
    __shared__ float vals[48];
    const int i = threadIdx.x;
    const float wts[5]  = {0.0448f, 0.2856f, 0.3001f, 0.2363f, 0.1333f};
    const float cnts[5] = {252004.f, 60516.f, 13924.f, 2916.f, 484.f}; // (H_l-10)^2
    if (i < 48) {
        float v = 1.f;
#pragma unroll
        for (int l = 0; l < 4; l++) {
            float cs = d_sums[(l * 48 + i) * 2 + 1] / cnts[l];
            cs = fmaxf(cs, 0.f);
            v *= powf(cs, wts[l]);
        }
        float dm = d_sums[(4 * 48 + i) * 2 + 0] / cnts[4];
        dm = fmaxf(dm, 0.f);
        v *= powf(dm, wts[4]);
        vals[i] = v;
    }
    __syncthreads();
    if (i == 0) {
        float s = 0.f;
        for (int j = 0; j < 48; j++) s += vals[j];
        float r = s / 48.f;
        for (int k = 0; k < out_size; k++) out[k] = r;
    }
}

extern "C" void kernel_launch(void* const* d_in, const int* in_sizes, int n_in,
                              void* d_out, int out_size)
{
    const float* X = (const float*)d_in[0];
    const float* Y = (const float*)d_in[1];
    float* out = (float*)d_out;

    float *Xp = nullptr, *Yp = nullptr;
    cudaGetSymbolAddress((void**)&Xp, d_Xp);
    cudaGetSymbolAddress((void**)&Yp, d_Yp);

    const size_t OFF1 = 0, OFF2 = 3145728, OFF3 = 3932160, OFF4 = 4128768;

    zero_sums_kernel<<<1, 512>>>();

    // level 0: 512 -> out 502 (16x16 tiles)
    ssim_stats_kernel<<<dim3(16, 16, 48), 256>>>(X, Y, 512, 512, 0);
    {
        int Ho = 256, total = 48 * Ho * Ho;
        pool_kernel<<<(total + 255) / 256, 256>>>(X, Y, Xp + OFF1, Yp + OFF1, Ho, 512);
    }
    // level 1: 256 -> out 246 (8x8 tiles)
    ssim_stats_kernel<<<dim3(8, 8, 48), 256>>>(Xp + OFF1, Yp + OFF1, 256, 256, 1);
    {
        int Ho = 128, total = 48 * Ho * Ho;
        pool_kernel<<<(total + 255) / 256, 256>>>(Xp + OFF1, Yp + OFF1, Xp + OFF2, Yp + OFF2, Ho, 256);
    }
    // level 2: 128 -> out 118 (4x4 tiles)
    ssim_stats_kernel<<<dim3(4, 4, 48), 256>>>(Xp + OFF2, Yp + OFF2, 128, 128, 2);
    {
        int Ho = 64, total = 48 * Ho * Ho;
        pool_kernel<<<(total + 255) / 256, 256>>>(Xp + OFF2, Yp + OFF2, Xp + OFF3, Yp + OFF3, Ho, 128);
    }
    // level 3: 64 -> out 54 (2x2 tiles)
    ssim_stats_kernel<<<dim3(2, 2, 48), 256>>>(Xp + OFF3, Yp + OFF3, 64, 64, 3);
    {
        int Ho = 32, total = 48 * Ho * Ho;
        pool_kernel<<<(total + 255) / 256, 256>>>(Xp + OFF3, Yp + OFF3, Xp + OFF4, Yp + OFF4, Ho, 64);
    }
    // level 4: 32 -> out 22 (1x1 tiles)
    ssim_stats_kernel<<<dim3(1, 1, 48), 256>>>(Xp + OFF4, Yp + OFF4, 32, 32, 4);

    final_kernel<<<1, 64>>>(out, out_size);
}

// round 2
// speedup vs baseline: 1.1331x; 1.1331x over previous
#include <cuda_runtime.h>
#include <math.h>

// ---------------------------------------------------------------------------
// MS-SSIM, 5 levels, inputs 16x3x512x512 fp32 (48 planes, square, even sizes).
// Per level ONE fused kernel: tile->SMEM, separable 11-tap blur of the 5 maps
// (mu1, mu2, E[XX], E[YY], E[XY]), epilogue, per-plane block reduction +
// atomicAdd, AND the 2x2 avg-pool for the next level (reusing the SMEM tile).
// Level 4 (1 block per image) additionally performs the weighted geometric
// combine and atomically accumulates the final mean into d_out.
// 6 launches total: zero, S0, S1, S2, S3, S4(+combine).
// Gaussian weights are compile-time literals -> FFMA-imm (2x issue rate).
// ---------------------------------------------------------------------------

#define TW 32
#define TH 32
#define EH 42          // TH + 10
#define EW 42          // TW + 10
#define EWP 43         // padded stride for input tiles (conflict-free)
#define HWP 33         // padded stride for horizontal-blur tiles

// gaussian(sigma=1.5, 11 taps), normalized (matches float32 reference ~1e-7)
#define G0 0.00102838f
#define G1 0.00759870f
#define G2 0.03600070f
#define G3 0.10936100f
#define G4 0.21300540f
#define G5 0.26601152f

// scratch for pooled pyramids (levels 1..4), 48 planes each
// L1: 48*256*256 = 3145728   (offset 0)
// L2: 48*128*128 =  786432   (offset 3145728)
// L3: 48*64*64   =  196608   (offset 3932160)
// L4: 48*32*32   =   49152   (offset 4128768)   total 4177920
__device__ __align__(16) float d_Xp[4177920];
__device__ __align__(16) float d_Yp[4177920];
__device__ float d_sums[480];   // [level(5)][img(48)][2: d_sum, cs_sum]

__global__ void zero_kernel(float* out, int out_size) {
    int i = threadIdx.x;
    if (i < 480) d_sums[i] = 0.f;
    if (i < out_size) out[i] = 0.f;
}

__global__ void __launch_bounds__(256) ssim_stats_kernel(
    const float* __restrict__ Xg, const float* __restrict__ Yg,
    float* __restrict__ Xo, float* __restrict__ Yo,   // pooled outputs (null-semantics via level==4)
    int H, int level, float* __restrict__ out, int out_size)
{
    __shared__ float sX[EH][EWP];
    __shared__ float sY[EH][EWP];
    __shared__ float sH[5][EH][HWP];   // gx, gy, gxx, gyy, gxy (h-blurred)
    __shared__ float red[2][8];

    const int W = H;
    const int outH = H - 10;
    const int img = blockIdx.z;
    const int tx0 = blockIdx.x * TW;
    const int ty0 = blockIdx.y * TH;
    const float* Xi = Xg + (size_t)img * H * W;
    const float* Yi = Yg + (size_t)img * H * W;
    const int tid = threadIdx.x;

    const float g[11] = {G0,G1,G2,G3,G4,G5,G4,G3,G2,G1,G0};

    // ---- load extended tile (clamped; clamped values only feed masked px) --
    for (int i = tid; i < EH * EW; i += 256) {
        int r = i / EW, c = i - r * EW;
        int gr = ty0 + r; if (gr > H - 1) gr = H - 1;
        int gc = tx0 + c; if (gc > W - 1) gc = W - 1;
        size_t off = (size_t)gr * W + gc;
        sX[r][c] = Xi[off];
        sY[r][c] = Yi[off];
    }
    __syncthreads();

    // ---- fused 2x2 avg-pool of the core 32x32 region -> next level ---------
    if (level < 4) {
        const int Hp = H >> 1;
        int ph = tid >> 4, pw = tid & 15;       // 16x16 pooled outputs
        int r2 = ph * 2, c2 = pw * 2;
        float px = 0.25f * ((sX[r2][c2] + sX[r2][c2 + 1]) + (sX[r2 + 1][c2] + sX[r2 + 1][c2 + 1]));
        float py = 0.25f * ((sY[r2][c2] + sY[r2][c2 + 1]) + (sY[r2 + 1][c2] + sY[r2 + 1][c2 + 1]));
        size_t po = (size_t)img * Hp * Hp + (size_t)(ty0 / 2 + ph) * Hp + (tx0 / 2 + pw);
        Xo[po] = px;
        Yo[po] = py;
    }

    // ---- horizontal blur: 42 rows x 32 cols, 4 consecutive cols per item ---
    for (int i = tid; i < EH * (TW / 4); i += 256) {
        int r = i >> 3, c4 = (i & 7) * 4;
        float bx[14], by[14];
#pragma unroll
        for (int j = 0; j < 14; j++) { bx[j] = sX[r][c4 + j]; by[j] = sY[r][c4 + j]; }
#pragma unroll
        for (int q = 0; q < 4; q++) {
            float gx = 0.f, gy = 0.f, gxx = 0.f, gyy = 0.f, gxy = 0.f;
#pragma unroll
            for (int k = 0; k < 11; k++) {
                float xv = bx[q + k], yv = by[q + k];
                float wx = g[k] * xv, wy = g[k] * yv;
                gx += wx; gy += wy;
                gxx = fmaf(wx, xv, gxx);
                gyy = fmaf(wy, yv, gyy);
                gxy = fmaf(wx, yv, gxy);
            }
            sH[0][r][c4 + q] = gx;
            sH[1][r][c4 + q] = gy;
            sH[2][r][c4 + q] = gxx;
            sH[3][r][c4 + q] = gyy;
            sH[4][r][c4 + q] = gxy;
        }
    }
    __syncthreads();

    // ---- vertical blur (4 consecutive rows per thread) + epilogue ----------
    const float C1 = 1e-4f, C2 = 9e-4f;
    float d_acc = 0.f, cs_acc = 0.f;
    const int ty = tid >> 5, tx = tid & 31;
    const int rbase = ty * 4;

    float m[5][4];
#pragma unroll
    for (int a = 0; a < 5; a++) {
        float buf[14];
#pragma unroll
        for (int j = 0; j < 14; j++) buf[j] = sH[a][rbase + j][tx];
#pragma unroll
        for (int q = 0; q < 4; q++) {
            float acc = 0.f;
#pragma unroll
            for (int k = 0; k < 11; k++) acc = fmaf(g[k], buf[q + k], acc);
            m[a][q] = acc;
        }
    }

    const int ocol = tx0 + tx;
#pragma unroll
    for (int q = 0; q < 4; q++) {
        int orow = ty0 + rbase + q;
        if (orow < outH && ocol < outH) {
            float mu1 = m[0][q], mu2 = m[1][q];
            float exx = m[2][q], eyy = m[3][q], exy = m[4][q];
            float mu1sq = mu1 * mu1, mu2sq = mu2 * mu2, mu12 = mu1 * mu2;
            float sig1 = exx - mu1sq, sig2 = eyy - mu2sq, sig12 = exy - mu12;
            float S1 = __fdividef(2.f * mu12 + C1, mu1sq + mu2sq + C1);
            float S2 = __fdividef(2.f * sig12 + C2, sig1 + sig2 + C2);
            float S = fminf(S1 + S2, 2.0f);
            d_acc += sqrtf(2.0f - S);
            cs_acc += S2;
        }
    }

    // ---- block reduce -------------------------------------------------------
#pragma unroll
    for (int o = 16; o > 0; o >>= 1) {
        d_acc  += __shfl_down_sync(0xffffffffu, d_acc,  o);
        cs_acc += __shfl_down_sync(0xffffffffu, cs_acc, o);
    }
    if (tx == 0) { red[0][ty] = d_acc; red[1][ty] = cs_acc; }
    __syncthreads();

    if (tid == 0) {
        float ds = 0.f, cs = 0.f;
#pragma unroll
        for (int j = 0; j < 8; j++) { ds += red[0][j]; cs += red[1][j]; }
        if (level < 4) {
            atomicAdd(&d_sums[(level * 48 + img) * 2 + 0], ds);
            atomicAdd(&d_sums[(level * 48 + img) * 2 + 1], cs);
        } else {
            // level 4: exactly one block per image -> no atomics needed for
            // own sums; all earlier levels' sums are complete (serialized
            // launches). Do the weighted geometric combine here.
            const float wts[5]  = {0.0448f, 0.2856f, 0.3001f, 0.2363f, 0.1333f};
            const float cnts[4] = {252004.f, 60516.f, 13924.f, 2916.f}; // (H_l-10)^2, l=0..3
            float v = 1.f;
#pragma unroll
            for (int l = 0; l < 4; l++) {
                float csm = d_sums[(l * 48 + img) * 2 + 1] / cnts[l];
                csm = fmaxf(csm, 0.f);
                v *= powf(csm, wts[l]);
            }
            float dm = fmaxf(ds / 484.f, 0.f);   // (32-10)^2 = 484
            v *= powf(dm, wts[4]);
            float contrib = v * (1.0f / 48.0f);
            for (int k = 0; k < out_size; k++) atomicAdd(&out[k], contrib);
        }
    }
}

extern "C" void kernel_launch(void* const* d_in, const int* in_sizes, int n_in,
                              void* d_out, int out_size)
{
    const float* X = (const float*)d_in[0];
    const float* Y = (const float*)d_in[1];
    float* out = (float*)d_out;

    float *Xp = nullptr, *Yp = nullptr;
    cudaGetSymbolAddress((void**)&Xp, d_Xp);
    cudaGetSymbolAddress((void**)&Yp, d_Yp);

    const size_t OFF1 = 0, OFF2 = 3145728, OFF3 = 3932160, OFF4 = 4128768;

    zero_kernel<<<1, 512>>>(out, out_size);

    // level 0: 512 (16x16 tiles), pools into L1 buffer
    ssim_stats_kernel<<<dim3(16, 16, 48), 256>>>(X, Y, Xp + OFF1, Yp + OFF1, 512, 0, out, out_size);
    // level 1: 256 (8x8 tiles)
    ssim_stats_kernel<<<dim3(8, 8, 48), 256>>>(Xp + OFF1, Yp + OFF1, Xp + OFF2, Yp + OFF2, 256, 1, out, out_size);
    // level 2: 128 (4x4 tiles)
    ssim_stats_kernel<<<dim3(4, 4, 48), 256>>>(Xp + OFF2, Yp + OFF2, Xp + OFF3, Yp + OFF3, 128, 2, out, out_size);
    // level 3: 64 (2x2 tiles)
    ssim_stats_kernel<<<dim3(2, 2, 48), 256>>>(Xp + OFF3, Yp + OFF3, Xp + OFF4, Yp + OFF4, 64, 3, out, out_size);
    // level 4: 32 (1x1 tiles) + final combine fused
    ssim_stats_kernel<<<dim3(1, 1, 48), 256>>>(Xp + OFF4, Yp + OFF4, nullptr, nullptr, 32, 4, out, out_size);
}

// round 3
// speedup vs baseline: 1.5510x; 1.3689x over previous
#include <cuda_runtime.h>
#include <math.h>

// ---------------------------------------------------------------------------
// MS-SSIM, 5 levels, 16x3x512x512 fp32 (48 planes). One fused kernel / level:
// tile->SMEM (packed (x,y) f32x2), separable 11-tap blur of 5 maps using
// Blackwell packed fma.rn.f32x2 (2 fp32 MACs / inst), epilogue, block reduce,
// fused 2x2 avg-pool for the next level. Level 4 also does the final combine.
// ---------------------------------------------------------------------------

typedef unsigned long long u64;

__device__ __forceinline__ u64 pack2(float lo, float hi) {
    u64 r; asm("mov.b64 %0,{%1,%2};" : "=l"(r) : "f"(lo), "f"(hi)); return r;
}
__device__ __forceinline__ void unpack2(u64 v, float& lo, float& hi) {
    asm("mov.b64 {%0,%1},%2;" : "=f"(lo), "=f"(hi) : "l"(v));
}
__device__ __forceinline__ u64 fma2(u64 a, u64 b, u64 c) {
    u64 d; asm("fma.rn.f32x2 %0,%1,%2,%3;" : "=l"(d) : "l"(a), "l"(b), "l"(c)); return d;
}
__device__ __forceinline__ u64 mul2(u64 a, u64 b) {
    u64 d; asm("mul.rn.f32x2 %0,%1,%2;" : "=l"(d) : "l"(a), "l"(b)); return d;
}
__device__ __forceinline__ u64 add2(u64 a, u64 b) {
    u64 d; asm("add.rn.f32x2 %0,%1,%2;" : "=l"(d) : "l"(a), "l"(b)); return d;
}
__device__ __forceinline__ float sqrt_fast(float x) {
    float r; asm("sqrt.approx.f32 %0,%1;" : "=f"(r) : "f"(x)); return r;
}

#define TW 32
#define TH 32
#define EH 42
#define EW 42
#define SIN_S 44       // u64 stride of input tile
#define SH_S  33       // stride of h-blurred maps

// gaussian(sigma=1.5, 11 taps), normalized
#define G_0 0.00102838f
#define G_1 0.00759876f
#define G_2 0.03600088f
#define G_3 0.10936090f
#define G_4 0.21300530f
#define G_5 0.26601160f

// pooled pyramids (levels 1..4), 48 planes each
__device__ __align__(16) float d_Xp[4177920];
__device__ __align__(16) float d_Yp[4177920];
__device__ float d_sums[480];   // [level][img][2]

__global__ void zero_kernel(float* out, int out_size) {
    int i = threadIdx.x;
    if (i < 480) d_sums[i] = 0.f;
    if (i < out_size) out[i] = 0.f;
}

__global__ void __launch_bounds__(256) ssim_stats_kernel(
    const float* __restrict__ Xg, const float* __restrict__ Yg,
    float* __restrict__ Xo, float* __restrict__ Yo,
    int H, int level, float* __restrict__ out, int out_size)
{
    __shared__ u64  sIN[EH * SIN_S];   // packed (x,y)
    __shared__ u64  sMU[EH * SH_S];    // h-blurred (gx,gy)
    __shared__ u64  sPP[EH * SH_S];    // h-blurred (E xx, E yy)
    __shared__ float sXYh[EH * SH_S];  // h-blurred E xy
    __shared__ float red[2][8];

    const int W = H;
    const int outH = H - 10;
    const int img = blockIdx.z;
    const int tx0 = blockIdx.x * TW;
    const int ty0 = blockIdx.y * TH;
    const float* Xi = Xg + (size_t)img * H * W;
    const float* Yi = Yg + (size_t)img * H * W;
    const int tid = threadIdx.x;

    const float gg[11] = {G_0,G_1,G_2,G_3,G_4,G_5,G_4,G_3,G_2,G_1,G_0};
    u64 G2r[11];
#pragma unroll
    for (int k = 0; k < 11; k++) G2r[k] = pack2(gg[k], gg[k]);

    // ---- load extended tile, packed (x,y) -----------------------------------
    const bool interior = (tx0 + EW <= W) && (ty0 + EH <= H);
    {
        int r = tid / EW, c = tid - r * EW;
        if (interior) {
            const float* xp = Xi + (size_t)(ty0 + r) * W + (tx0 + c);
            const float* yp = Yi + (size_t)(ty0 + r) * W + (tx0 + c);
            int rr = r, cc = c;
#pragma unroll
            for (int it = 0; it < 7; it++) {
                if (it < 6 || tid < (EH * EW - 6 * 256)) {
                    sIN[rr * SIN_S + cc] = pack2(__ldg(xp), __ldg(yp));
                }
                cc += 4; rr += 6;
                xp += 6 * (size_t)W + 4; yp += 6 * (size_t)W + 4;
                if (cc >= EW) { cc -= EW; rr += 1; xp += W - EW; yp += W - EW; }
            }
        } else {
            for (int i = tid; i < EH * EW; i += 256) {
                int r2 = i / EW, c2 = i - r2 * EW;
                int gr = ty0 + r2; if (gr > H - 1) gr = H - 1;
                int gc = tx0 + c2; if (gc > W - 1) gc = W - 1;
                sIN[r2 * SIN_S + c2] = pack2(Xi[(size_t)gr * W + gc], Yi[(size_t)gr * W + gc]);
            }
        }
    }
    __syncthreads();

    // ---- fused 2x2 avg-pool of core 32x32 -> next level ---------------------
    if (level < 4) {
        const int Hp = H >> 1;
        int ph = tid >> 4, pw = tid & 15;
        const u64* p0 = sIN + (ph * 2) * SIN_S + pw * 2;
        u64 s = add2(add2(p0[0], p0[1]), add2(p0[SIN_S], p0[SIN_S + 1]));
        float px, py; unpack2(s, px, py);
        size_t po = (size_t)img * Hp * Hp + (size_t)(ty0 / 2 + ph) * Hp + (tx0 / 2 + pw);
        Xo[po] = 0.25f * px;
        Yo[po] = 0.25f * py;
    }

    // ---- horizontal blur: 42 rows x 8 col-groups (4 outputs each) -----------
    {
        auto hblur = [&](int item) {
            int r = item >> 3, c4 = (item & 7) << 2;
            const u64* row = sIN + r * SIN_S + c4;
            u64 aMU[4] = {0,0,0,0}, aPP[4] = {0,0,0,0};
            float aXY[4] = {0.f,0.f,0.f,0.f};
#pragma unroll
            for (int k = 0; k < 14; k++) {
                u64 v = row[k];
                u64 pp = mul2(v, v);
                float vx, vy; unpack2(v, vx, vy);
                float pxy = vx * vy;
#pragma unroll
                for (int q = 0; q < 4; q++) {
                    int t = k - q;
                    if (t >= 0 && t < 11) {
                        aMU[q] = fma2(v,  G2r[t], aMU[q]);
                        aPP[q] = fma2(pp, G2r[t], aPP[q]);
                        aXY[q] = fmaf(pxy, gg[t], aXY[q]);
                    }
                }
            }
            int o = r * SH_S + c4;
#pragma unroll
            for (int q = 0; q < 4; q++) {
                sMU[o + q] = aMU[q];
                sPP[o + q] = aPP[q];
                sXYh[o + q] = aXY[q];
            }
        };
        hblur(tid);
        if (tid < EH * 8 - 256) hblur(tid + 256);
    }
    __syncthreads();

    // ---- vertical blur (4 rows per thread) + epilogue ------------------------
    const float C1 = 1e-4f, C2 = 9e-4f;
    float d_acc = 0.f, cs_acc = 0.f;
    const int ty = tid >> 5, tx = tid & 31;
    const int rbase = ty * 4;
    {
        u64 aMU[4] = {0,0,0,0}, aPP[4] = {0,0,0,0};
        float aXY[4] = {0.f,0.f,0.f,0.f};
#pragma unroll
        for (int k = 0; k < 14; k++) {
            int row = (rbase + k) * SH_S + tx;
            u64 mu = sMU[row];
            u64 pp = sPP[row];
            float xy = sXYh[row];
#pragma unroll
            for (int q = 0; q < 4; q++) {
                int t = k - q;
                if (t >= 0 && t < 11) {
                    aMU[q] = fma2(mu, G2r[t], aMU[q]);
                    aPP[q] = fma2(pp, G2r[t], aPP[q]);
                    aXY[q] = fmaf(xy, gg[t], aXY[q]);
                }
            }
        }
        const int ocol = tx0 + tx;
#pragma unroll
        for (int q = 0; q < 4; q++) {
            int orow = ty0 + rbase + q;
            if (orow < outH && ocol < outH) {
                float mu1, mu2, exx, eyy;
                unpack2(aMU[q], mu1, mu2);
                unpack2(aPP[q], exx, eyy);
                float exy = aXY[q];
                float mu1sq = mu1 * mu1, mu2sq = mu2 * mu2, mu12 = mu1 * mu2;
                float sig1 = exx - mu1sq, sig2 = eyy - mu2sq, sig12 = exy - mu12;
                float S1 = __fdividef(2.f * mu12 + C1, mu1sq + mu2sq + C1);
                float S2 = __fdividef(2.f * sig12 + C2, sig1 + sig2 + C2);
                float S = fminf(S1 + S2, 2.0f);
                d_acc += sqrt_fast(2.0f - S);
                cs_acc += S2;
            }
        }
    }

    // ---- block reduce --------------------------------------------------------
#pragma unroll
    for (int o = 16; o > 0; o >>= 1) {
        d_acc  += __shfl_down_sync(0xffffffffu, d_acc,  o);
        cs_acc += __shfl_down_sync(0xffffffffu, cs_acc, o);
    }
    if (tx == 0) { red[0][ty] = d_acc; red[1][ty] = cs_acc; }
    __syncthreads();

    if (tid == 0) {
        float ds = 0.f, cs = 0.f;
#pragma unroll
        for (int j = 0; j < 8; j++) { ds += red[0][j]; cs += red[1][j]; }
        if (level < 4) {
            atomicAdd(&d_sums[(level * 48 + img) * 2 + 0], ds);
            atomicAdd(&d_sums[(level * 48 + img) * 2 + 1], cs);
        } else {
            const float wts[5]  = {0.0448f, 0.2856f, 0.3001f, 0.2363f, 0.1333f};
            const float cnts[4] = {252004.f, 60516.f, 13924.f, 2916.f};
            float v = 1.f;
#pragma unroll
            for (int l = 0; l < 4; l++) {
                float csm = d_sums[(l * 48 + img) * 2 + 1] / cnts[l];
                csm = fmaxf(csm, 0.f);
                v *= powf(csm, wts[l]);
            }
            float dm = fmaxf(ds / 484.f, 0.f);   // (32-10)^2
            v *= powf(dm, wts[4]);
            float contrib = v * (1.0f / 48.0f);
            for (int k = 0; k < out_size; k++) atomicAdd(&out[k], contrib);
        }
    }
}

extern "C" void kernel_launch(void* const* d_in, const int* in_sizes, int n_in,
                              void* d_out, int out_size)
{
    const float* X = (const float*)d_in[0];
    const float* Y = (const float*)d_in[1];
    float* out = (float*)d_out;

    float *Xp = nullptr, *Yp = nullptr;
    cudaGetSymbolAddress((void**)&Xp, d_Xp);
    cudaGetSymbolAddress((void**)&Yp, d_Yp);

    const size_t OFF1 = 0, OFF2 = 3145728, OFF3 = 3932160, OFF4 = 4128768;

    zero_kernel<<<1, 512>>>(out, out_size);

    ssim_stats_kernel<<<dim3(16, 16, 48), 256>>>(X, Y, Xp + OFF1, Yp + OFF1, 512, 0, out, out_size);
    ssim_stats_kernel<<<dim3(8, 8, 48), 256>>>(Xp + OFF1, Yp + OFF1, Xp + OFF2, Yp + OFF2, 256, 1, out, out_size);
    ssim_stats_kernel<<<dim3(4, 4, 48), 256>>>(Xp + OFF2, Yp + OFF2, Xp + OFF3, Yp + OFF3, 128, 2, out, out_size);
    ssim_stats_kernel<<<dim3(2, 2, 48), 256>>>(Xp + OFF3, Yp + OFF3, Xp + OFF4, Yp + OFF4, 64, 3, out, out_size);
    ssim_stats_kernel<<<dim3(1, 1, 48), 256>>>(Xp + OFF4, Yp + OFF4, nullptr, nullptr, 32, 4, out, out_size);
}

// round 4
// speedup vs baseline: 1.8407x; 1.1868x over previous
#include <cuda_runtime.h>
#include <math.h>

// ---------------------------------------------------------------------------
// MS-SSIM, 5 levels, 16x3x512x512 fp32 (48 planes).
// 4 launches: zero, ssim_level0 (+ full pool pyramid L1..L4 fused),
// ssim_rest (levels 1..4 in ONE grid), final combine.
// Blur uses 2 packed f32x2 streams: (x,y) and (x^2+y^2, x*y)  -- the epilogue
// only needs sigma1_sq + sigma2_sq, so 4 maps suffice instead of 5.
// ---------------------------------------------------------------------------

typedef unsigned long long u64;

__device__ __forceinline__ u64 pack2(float lo, float hi) {
    u64 r; asm("mov.b64 %0,{%1,%2};" : "=l"(r) : "f"(lo), "f"(hi)); return r;
}
__device__ __forceinline__ void unpack2(u64 v, float& lo, float& hi) {
    asm("mov.b64 {%0,%1},%2;" : "=f"(lo), "=f"(hi) : "l"(v));
}
__device__ __forceinline__ u64 fma2(u64 a, u64 b, u64 c) {
    u64 d; asm("fma.rn.f32x2 %0,%1,%2,%3;" : "=l"(d) : "l"(a), "l"(b), "l"(c)); return d;
}
__device__ __forceinline__ u64 mul2(u64 a, u64 b) {
    u64 d; asm("mul.rn.f32x2 %0,%1,%2;" : "=l"(d) : "l"(a), "l"(b)); return d;
}
__device__ __forceinline__ u64 add2(u64 a, u64 b) {
    u64 d; asm("add.rn.f32x2 %0,%1,%2;" : "=l"(d) : "l"(a), "l"(b)); return d;
}
__device__ __forceinline__ float sqrt_fast(float x) {
    float r; asm("sqrt.approx.f32 %0,%1;" : "=f"(r) : "f"(x)); return r;
}

#define TW 32
#define TH 32
#define EH 42
#define EW 42
#define SIN_S 44       // u64 stride of input tile
#define SH_S  33       // stride of h-blurred maps

// gaussian(sigma=1.5, 11 taps), normalized
#define G_0 0.00102838f
#define G_1 0.00759876f
#define G_2 0.03600088f
#define G_3 0.10936090f
#define G_4 0.21300530f
#define G_5 0.26601160f

// pooled pyramids (levels 1..4), 48 planes each
// L1: 48*256*256 = 3145728 @0 ; L2 @3145728 ; L3 @3932160 ; L4 @4128768
__device__ __align__(16) float d_Xp[4177920];
__device__ __align__(16) float d_Yp[4177920];
__device__ float d_sums[480];   // [level][img][2]

#define OFF1 0
#define OFF2 3145728
#define OFF3 3932160
#define OFF4 4128768

__global__ void zero_kernel() {
    int i = threadIdx.x;
    if (i < 480) d_sums[i] = 0.f;
}

// core tile worker. POOL => level 0 (H=512, also emits L1..L4 pyramid).
template <bool POOL>
__device__ __forceinline__ void ssim_tile(
    const float* __restrict__ Xi, const float* __restrict__ Yi,
    int H, int level, int img, int bx, int by,
    float* __restrict__ Xp, float* __restrict__ Yp)
{
    __shared__ u64 sIN[EH * SIN_S];   // packed (x,y)
    __shared__ u64 sMU[EH * SH_S];    // h-blurred (gx,gy)
    __shared__ u64 sSP[EH * SH_S];    // h-blurred (E[xx+yy], E[xy])
    __shared__ u64 sL2[64];
    __shared__ float red[2][8];

    const int W = H;
    const int outH = H - 10;
    const int tx0 = bx * TW;
    const int ty0 = by * TH;
    const int tid = threadIdx.x;

    const float gg[11] = {G_0,G_1,G_2,G_3,G_4,G_5,G_4,G_3,G_2,G_1,G_0};
    u64 G2r[11];
#pragma unroll
    for (int k = 0; k < 11; k++) G2r[k] = pack2(gg[k], gg[k]);

    // ---- load extended tile, packed (x,y) -----------------------------------
    const bool interior = (tx0 + EW <= W) && (ty0 + EH <= H);
    {
        int r = tid / EW, c = tid - r * EW;
        if (interior) {
            const float* xp = Xi + (size_t)(ty0 + r) * W + (tx0 + c);
            const float* yp = Yi + (size_t)(ty0 + r) * W + (tx0 + c);
            int rr = r, cc = c;
#pragma unroll
            for (int it = 0; it < 7; it++) {
                if (it < 6 || tid < (EH * EW - 6 * 256)) {
                    sIN[rr * SIN_S + cc] = pack2(__ldg(xp), __ldg(yp));
                }
                cc += 4; rr += 6;
                xp += 6 * (size_t)W + 4; yp += 6 * (size_t)W + 4;
                if (cc >= EW) { cc -= EW; rr += 1; xp += W - EW; yp += W - EW; }
            }
        } else {
            for (int i = tid; i < EH * EW; i += 256) {
                int r2 = i / EW, c2 = i - r2 * EW;
                int gr = ty0 + r2; if (gr > H - 1) gr = H - 1;
                int gc = tx0 + c2; if (gc > W - 1) gc = W - 1;
                sIN[r2 * SIN_S + c2] = pack2(Xi[(size_t)gr * W + gc], Yi[(size_t)gr * W + gc]);
            }
        }
    }
    __syncthreads();

    // ---- fused pool pyramid (level 0 only): L1..L4, all local to tile -------
    if (POOL) {
        const u64 QUARTER = pack2(0.25f, 0.25f);
        const int lane = tid & 31;
        // L1: one 2x2 per thread; tid = ph*16+pw
        int ph = tid >> 4, pw = tid & 15;
        const u64* p0 = sIN + (ph * 2) * SIN_S + pw * 2;
        u64 v1 = mul2(add2(add2(p0[0], p0[1]), add2(p0[SIN_S], p0[SIN_S + 1])), QUARTER);
        {
            float a, b; unpack2(v1, a, b);
            size_t po = (size_t)img * 65536 + (size_t)(by * 16 + ph) * 256 + (bx * 16 + pw);
            (Xp + OFF1)[po] = a; (Yp + OFF1)[po] = b;
        }
        // L2 via intra-warp shuffles: owner lanes have bit0=bit4=0
        u64 s2 = add2(v1, __shfl_xor_sync(0xffffffffu, v1, 1));
        s2 = add2(s2, __shfl_xor_sync(0xffffffffu, s2, 16));
        if ((lane & 17) == 0) {
            u64 v2 = mul2(s2, QUARTER);
            int qh = tid >> 5, qw = lane >> 1;
            float a, b; unpack2(v2, a, b);
            size_t po = (size_t)img * 16384 + (size_t)(by * 8 + qh) * 128 + (bx * 8 + qw);
            (Xp + OFF2)[po] = a; (Yp + OFF2)[po] = b;
            sL2[qh * 8 + qw] = v2;
        }
    }

    // ---- horizontal blur: 42 rows x 8 col-groups (4 outputs each) -----------
    {
        auto hblur = [&](int item) {
            int r = item >> 3, c4 = (item & 7) << 2;
            const u64* row = sIN + r * SIN_S + c4;
            u64 aMU[4] = {0,0,0,0}, aSP[4] = {0,0,0,0};
#pragma unroll
            for (int k = 0; k < 14; k++) {
                u64 v = row[k];
                u64 xy2 = mul2(v, v);
                float xx, yy, vx, vy;
                unpack2(xy2, xx, yy);
                unpack2(v, vx, vy);
                u64 sp = pack2(xx + yy, vx * vy);
#pragma unroll
                for (int q = 0; q < 4; q++) {
                    int t = k - q;
                    if (t >= 0 && t < 11) {
                        aMU[q] = fma2(v,  G2r[t], aMU[q]);
                        aSP[q] = fma2(sp, G2r[t], aSP[q]);
                    }
                }
            }
            int o = r * SH_S + c4;
#pragma unroll
            for (int q = 0; q < 4; q++) {
                sMU[o + q] = aMU[q];
                sSP[o + q] = aSP[q];
            }
        };
        hblur(tid);
        if (tid < EH * 8 - 256) hblur(tid + 256);
    }
    __syncthreads();

    // ---- pyramid tail: L3 (16 threads) + L4 (shuffles in half-warp) ---------
    if (POOL && tid < 16) {
        const u64 QUARTER = pack2(0.25f, 0.25f);
        int rh = tid >> 2, rw = tid & 3;
        const u64* q0 = sL2 + (rh * 2) * 8 + rw * 2;
        u64 v3 = mul2(add2(add2(q0[0], q0[1]), add2(q0[8], q0[9])), QUARTER);
        {
            float a, b; unpack2(v3, a, b);
            size_t po = (size_t)img * 4096 + (size_t)(by * 4 + rh) * 64 + (bx * 4 + rw);
            (Xp + OFF3)[po] = a; (Yp + OFF3)[po] = b;
        }
        u64 s4 = add2(v3, __shfl_xor_sync(0xffffu, v3, 1));
        s4 = add2(s4, __shfl_xor_sync(0xffffu, s4, 4));
        if ((tid & 5) == 0) {
            u64 v4 = mul2(s4, QUARTER);
            int sh = tid >> 3, sw = (tid >> 1) & 1;
            float a, b; unpack2(v4, a, b);
            size_t po = (size_t)img * 1024 + (size_t)(by * 2 + sh) * 32 + (bx * 2 + sw);
            (Xp + OFF4)[po] = a; (Yp + OFF4)[po] = b;
        }
    }

    // ---- vertical blur (4 rows per thread) + epilogue ------------------------
    const float C1 = 1e-4f, C2 = 9e-4f;
    float d_acc = 0.f, cs_acc = 0.f;
    const int ty = tid >> 5, tx = tid & 31;
    const int rbase = ty * 4;
    {
        u64 aMU[4] = {0,0,0,0}, aSP[4] = {0,0,0,0};
#pragma unroll
        for (int k = 0; k < 14; k++) {
            int row = (rbase + k) * SH_S + tx;
            u64 mu = sMU[row];
            u64 sp = sSP[row];
#pragma unroll
            for (int q = 0; q < 4; q++) {
                int t = k - q;
                if (t >= 0 && t < 11) {
                    aMU[q] = fma2(mu, G2r[t], aMU[q]);
                    aSP[q] = fma2(sp, G2r[t], aSP[q]);
                }
            }
        }
        const int ocol = tx0 + tx;
#pragma unroll
        for (int q = 0; q < 4; q++) {
            int orow = ty0 + rbase + q;
            if (orow < outH && ocol < outH) {
                float mu1, mu2, ess, exy;
                unpack2(aMU[q], mu1, mu2);
                unpack2(aSP[q], ess, exy);
                float mu1sq = mu1 * mu1, mu2sq = mu2 * mu2, mu12 = mu1 * mu2;
                float sig_sum = ess - mu1sq - mu2sq;
                float sig12 = exy - mu12;
                float S1 = __fdividef(2.f * mu12 + C1, mu1sq + mu2sq + C1);
                float S2 = __fdividef(2.f * sig12 + C2, sig_sum + C2);
                float S = fminf(S1 + S2, 2.0f);
                d_acc += sqrt_fast(2.0f - S);
                cs_acc += S2;
            }
        }
    }

    // ---- block reduce + atomic ------------------------------------------------
#pragma unroll
    for (int o = 16; o > 0; o >>= 1) {
        d_acc  += __shfl_down_sync(0xffffffffu, d_acc,  o);
        cs_acc += __shfl_down_sync(0xffffffffu, cs_acc, o);
    }
    if (tx == 0) { red[0][ty] = d_acc; red[1][ty] = cs_acc; }
    __syncthreads();
    if (tid == 0) {
        float ds = 0.f, cs = 0.f;
#pragma unroll
        for (int j = 0; j < 8; j++) { ds += red[0][j]; cs += red[1][j]; }
        atomicAdd(&d_sums[(level * 48 + img) * 2 + 0], ds);
        atomicAdd(&d_sums[(level * 48 + img) * 2 + 1], cs);
    }
}

__global__ void __launch_bounds__(256) ssim_level0_kernel(
    const float* __restrict__ X, const float* __restrict__ Y,
    float* __restrict__ Xp, float* __restrict__ Yp)
{
    const int img = blockIdx.z;
    const float* Xi = X + (size_t)img * 512 * 512;
    const float* Yi = Y + (size_t)img * 512 * 512;
    ssim_tile<true>(Xi, Yi, 512, 0, img, blockIdx.x, blockIdx.y, Xp, Yp);
}

// levels 1..4 in one grid of 4080 blocks
__global__ void __launch_bounds__(256) ssim_rest_kernel(
    const float* __restrict__ Xp, const float* __restrict__ Yp)
{
    int b = blockIdx.x;
    int level, H, nt, off, base;
    if (b < 3072)      { level = 1; H = 256; nt = 8; off = OFF1; base = 0; }
    else if (b < 3840) { level = 2; H = 128; nt = 4; off = OFF2; base = 3072; }
    else if (b < 4032) { level = 3; H = 64;  nt = 2; off = OFF3; base = 3840; }
    else               { level = 4; H = 32;  nt = 1; off = OFF4; base = 4032; }
    int rem = b - base;
    int tiles = nt * nt;
    int img = rem / tiles;
    int t = rem - img * tiles;
    int by = t / nt;
    int bx = t - by * nt;
    const float* Xi = Xp + off + (size_t)img * H * H;
    const float* Yi = Yp + off + (size_t)img * H * H;
    ssim_tile<false>(Xi, Yi, H, level, img, bx, by, nullptr, nullptr);
}

__global__ void final_kernel(float* out, int out_size)
{
    __shared__ float vals[48];
    const int i = threadIdx.x;
    const float wts[5]  = {0.0448f, 0.2856f, 0.3001f, 0.2363f, 0.1333f};
    const float cnts[5] = {252004.f, 60516.f, 13924.f, 2916.f, 484.f};
    if (i < 48) {
        float v = 1.f;
#pragma unroll
        for (int l = 0; l < 4; l++) {
            float csm = d_sums[(l * 48 + i) * 2 + 1] / cnts[l];
            csm = fmaxf(csm, 0.f);
            v *= powf(csm, wts[l]);
        }
        float dm = fmaxf(d_sums[(4 * 48 + i) * 2 + 0] / cnts[4], 0.f);
        v *= powf(dm, wts[4]);
        vals[i] = v;
    }
    __syncthreads();
    if (i == 0) {
        float s = 0.f;
        for (int j = 0; j < 48; j++) s += vals[j];
        float r = s / 48.f;
        for (int k = 0; k < out_size; k++) out[k] = r;
    }
}

extern "C" void kernel_launch(void* const* d_in, const int* in_sizes, int n_in,
                              void* d_out, int out_size)
{
    const float* X = (const float*)d_in[0];
    const float* Y = (const float*)d_in[1];
    float* out = (float*)d_out;

    float *Xp = nullptr, *Yp = nullptr;
    cudaGetSymbolAddress((void**)&Xp, d_Xp);
    cudaGetSymbolAddress((void**)&Yp, d_Yp);

    zero_kernel<<<1, 512>>>();
    ssim_level0_kernel<<<dim3(16, 16, 48), 256>>>(X, Y, Xp, Yp);
    ssim_rest_kernel<<<4080, 256>>>(Xp, Yp);
    final_kernel<<<1, 64>>>(out, out_size);
}